// round 10
// baseline (speedup 1.0000x reference)
#include <cuda_runtime.h>

#define B_SZ 8192
#define T_SZ 32

// Static device scratch
__device__ float d_Tp[27 * 20];                 // [mx][k], k = mh*2+j, pads 0
__device__ float d_To[9];                       // readout tensor
__device__ float4 d_S4[T_SZ * 5 * B_SZ];        // [t][q][b] float4 (21MB)

__device__ __forceinline__ float2 cmul(float2 a, float2 b) {
    return make_float2(a.x * b.x - a.y * b.y, a.x * b.y + a.y * b.x);
}
__device__ __forceinline__ unsigned long long fma2(unsigned long long a,
                                                   unsigned long long b,
                                                   unsigned long long c) {
    unsigned long long d;
    asm("fma.rn.f32x2 %0, %1, %2, %3;" : "=l"(d) : "l"(a), "l"(b), "l"(c));
    return d;
}
__device__ __forceinline__ unsigned long long pk2(float x) {
    unsigned long long r;
    asm("mov.b64 %0, {%1, %1};" : "=l"(r) : "f"(x));
    return r;
}
__device__ __forceinline__ void cpa16(void* smem, const void* gmem) {
    unsigned s = (unsigned)__cvta_generic_to_shared(smem);
    asm volatile("cp.async.cg.shared.global [%0], [%1], 16;"
                 :: "r"(s), "l"(gmem) : "memory");
}
__device__ __forceinline__ void pdl_trigger() {
    asm volatile("griddepcontrol.launch_dependents;");
}
__device__ __forceinline__ void pdl_wait() {
    asm volatile("griddepcontrol.wait;" ::: "memory");
}

// ---------------------------------------------------------------------------
// Precompute, xmask-split + shuffle-built U: 9 blocks x 256 threads.
//   Blocks 0..7: warp w owns U-columns 4w..4w+3 in registers (lane = row);
//                gates & CNOT rings via shfl (barrier-free); then U -> smem,
//                M-diagonals for 4 xmasks, T slice. 3 barriers total.
//   Block 8:     readout tensor To.
// ---------------------------------------------------------------------------
__global__ void __launch_bounds__(256) precompute_kernel(const float* __restrict__ wrec,
                                                         const float* __restrict__ wout) {
    pdl_trigger();
    const int tid = threadIdx.x;
    const int blk = blockIdx.x;

    // ================= block 8: readout tensor =================
    if (blk == 8) {
        if (tid < 9) {
            int m = tid;
            float2 V[4][4];
#pragma unroll
            for (int c2 = 0; c2 < 4; c2++)
#pragma unroll
                for (int r2 = 0; r2 < 4; r2++)
                    V[c2][r2] = make_float2(c2 == r2 ? 1.f : 0.f, 0.f);
#pragma unroll
            for (int l = 0; l < 2; l++) {
#pragma unroll
                for (int w = 0; w < 2; w++) {
                    float phi = wout[(l * 2 + w) * 3 + 0];
                    float th  = wout[(l * 2 + w) * 3 + 1];
                    float om  = wout[(l * 2 + w) * 3 + 2];
                    float s, c, sa, ca, sb, cb;
                    __sincosf(0.5f * th, &s, &c);
                    __sincosf(0.5f * (phi + om), &sa, &ca);
                    __sincosf(0.5f * (phi - om), &sb, &cb);
                    float2 r00 = make_float2( c * ca, -c * sa);
                    float2 r01 = make_float2(-s * cb, -s * sb);
                    float2 r10 = make_float2( s * cb, -s * sb);
                    float2 r11 = make_float2( c * ca,  c * sa);
                    int mask = 1 << (1 - w);
#pragma unroll
                    for (int col = 0; col < 4; col++) {
#pragma unroll
                        for (int i0 = 0; i0 < 4; i0++) {
                            if (i0 & mask) continue;
                            int i1 = i0 | mask;
                            float2 a0 = V[col][i0], a1 = V[col][i1];
                            float2 n0 = cmul(r00, a0), u01 = cmul(r01, a1);
                            n0.x += u01.x; n0.y += u01.y;
                            float2 n1 = cmul(r10, a0), u11 = cmul(r11, a1);
                            n1.x += u11.x; n1.y += u11.y;
                            V[col][i0] = n0;
                            V[col][i1] = n1;
                        }
                    }
                }
#pragma unroll
                for (int w = 0; w < 2; w++) {
                    int cm = 1 << (1 - w), tm = 1 << (1 - ((w + 1) & 1));
#pragma unroll
                    for (int col = 0; col < 4; col++)
#pragma unroll
                        for (int row = 0; row < 4; row++)
                            if ((row & cm) && !(row & tm)) {
                                float2 a = V[col][row], b2 = V[col][row | tm];
                                V[col][row] = b2;
                                V[col][row | tm] = a;
                            }
                }
            }
            float Mo[4][4];
#pragma unroll
            for (int s = 0; s < 4; s++)
#pragma unroll
                for (int t = 0; t < 4; t++) {
                    float acc = 0.f;
#pragma unroll
                    for (int k = 0; k < 4; k++) {
                        float2 vs = V[s][k], vt = V[t][k];
                        float re = vs.x * vt.x + vs.y * vt.y;
                        acc += ((k >> 1) & 1) ? -re : re;
                    }
                    Mo[s][t] = acc;
                }
            int d0 = m / 3, d1 = m % 3;
            int emask = (d0 == 1 ? 2 : 0) | (d1 == 1 ? 1 : 0);
            int xmask = (d0 == 2 ? 2 : 0) | (d1 == 2 ? 1 : 0);
            float sum = 0.f;
#pragma unroll
            for (int u = 0; u < 4; u++) {
                float sgn = (__popc(u & emask) & 1) ? -1.f : 1.f;
                sum += sgn * Mo[u][u ^ xmask];
            }
            d_To[m] = sum * 0.25f;
        }
        return;
    }

    // ================= blocks 0..7 =================
    __shared__ float2 G[10][4];
    __shared__ float UsR[32][33];
    __shared__ float UsI[32][33];
    __shared__ float sdiag[8][32];     // [wid = j*4+xmi][u]

    const int lane = tid & 31;
    const int wid  = tid >> 5;

    if (tid < 10) {
        float phi = wrec[tid * 3 + 0];
        float th  = wrec[tid * 3 + 1];
        float om  = wrec[tid * 3 + 2];
        float s, c, sa, ca, sb, cb;
        __sincosf(0.5f * th, &s, &c);
        __sincosf(0.5f * (phi + om), &sa, &ca);
        __sincosf(0.5f * (phi - om), &sb, &cb);
        G[tid][0] = make_float2( c * ca, -c * sa);
        G[tid][1] = make_float2(-s * cb, -s * sb);
        G[tid][2] = make_float2( s * cb, -s * sb);
        G[tid][3] = make_float2( c * ca,  c * sa);
    }
    __syncthreads();

    // ---- shuffle statevector gate build: warp wid owns cols 4wid..4wid+3,
    //      lane = row. Barrier-free. ----
    const int colbase = wid * 4;
    float ar[4], ai[4];
#pragma unroll
    for (int cc = 0; cc < 4; cc++) {
        ar[cc] = (lane == colbase + cc) ? 1.f : 0.f;
        ai[cc] = 0.f;
    }

#pragma unroll
    for (int l = 0; l < 2; l++) {
#pragma unroll
        for (int w = 0; w < 5; w++) {
            const int m = 1 << (4 - w);
            const int gi = l * 5 + w;
            float2 g00 = G[gi][0], g01 = G[gi][1];
            float2 g10 = G[gi][2], g11 = G[gi][3];
            bool hi = (lane & m) != 0;
            float cSx = hi ? g11.x : g00.x;
            float cSy = hi ? g11.y : g00.y;
            float cPx = hi ? g10.x : g01.x;
            float cPy = hi ? g10.y : g01.y;
#pragma unroll
            for (int cc = 0; cc < 4; cc++) {
                float arp = __shfl_xor_sync(0xffffffffu, ar[cc], m);
                float aip = __shfl_xor_sync(0xffffffffu, ai[cc], m);
                float nr = cSx * ar[cc] - cSy * ai[cc] + cPx * arp - cPy * aip;
                float ni = cSx * ai[cc] + cSy * ar[cc] + cPx * aip + cPy * arp;
                ar[cc] = nr;
                ai[cc] = ni;
            }
        }
        // CNOT ring (range l+1): new[u] = old[perm(u)] -> index shuffle
        {
            int rr = l + 1;
            int j = lane;
#pragma unroll
            for (int w = 4; w >= 0; w--) {
                int cm = 1 << (4 - w);
                int tm = 1 << (4 - ((w + rr) % 5));
                if (j & cm) j ^= tm;
            }
#pragma unroll
            for (int cc = 0; cc < 4; cc++) {
                ar[cc] = __shfl_sync(0xffffffffu, ar[cc], j);
                ai[cc] = __shfl_sync(0xffffffffu, ai[cc], j);
            }
        }
    }

    // write U to smem (row = lane, stride-33 -> conflict-free)
#pragma unroll
    for (int cc = 0; cc < 4; cc++) {
        UsR[lane][colbase + cc] = ar[cc];
        UsI[lane][colbase + cc] = ai[cc];
    }
    __syncthreads();

    // M-diagonals: thread (j, xmi, u) computes M_j[u][u^xm]
    {
        int j   = tid >> 7;          // 0..1
        int xmi = (tid >> 5) & 3;    // 0..3
        int u   = tid & 31;
        int xm  = blk * 4 + xmi;
        int v   = u ^ xm;
        float acc = 0.f;
#pragma unroll
        for (int k = 0; k < 32; k++) {
            float re = UsR[k][u] * UsR[k][v] + UsI[k][u] * UsI[k][v];
            int sbit = (j ? k : (k >> 1)) & 1;
            acc += sbit ? -re : re;
        }
        sdiag[tid >> 5][u] = acc;
    }
    __syncthreads();

    // T slice: warp wid = (j, xmi); lane = emask index over complement bits
    {
        int j   = wid >> 2;
        int xm  = blk * 4 + (wid & 3);
        int C   = (~xm) & 31;
        int nE  = 1 << (5 - __popc(xm));
        if (lane < nE) {
            int e = 0, rem = lane;
#pragma unroll
            for (int p = 0; p < 5; p++) {
                if (C & (1 << p)) {
                    if (rem & 1) e |= 1 << p;
                    rem >>= 1;
                }
            }
            float sum = 0.f;
#pragma unroll
            for (int u = 0; u < 32; u++) {
                float sgn = (__popc(u & e) & 1) ? -1.f : 1.f;
                sum += sgn * sdiag[wid][u];
            }
            int m = 0, p3 = 1;
#pragma unroll
            for (int p = 0; p < 5; p++) {
                int t3 = (xm & (1 << p)) ? 2 : ((e & (1 << p)) ? 1 : 0);
                m += t3 * p3;
                p3 *= 3;
            }
            d_Tp[(m / 9) * 20 + (m % 9) * 2 + j] = sum * (1.f / 32.f);
        }
    }

    // zero pads (block 0) — keeps Ts loads deterministic
    if (blk == 0 && tid < 54) {
        d_Tp[(tid >> 1) * 20 + 18 + (tid & 1)] = 0.f;
    }
}

// ---------------------------------------------------------------------------
// Phase 1 (PDL): prework before wait; minimal 243-fma2 contraction after.
// ---------------------------------------------------------------------------
__global__ void __launch_bounds__(256) phase1_kernel(const float* __restrict__ x_seq) {
    __shared__ __align__(16) float Ts[27 * 20];
    const int tid = threadIdx.x;

    int e = blockIdx.x * 256 + tid;
    int b = e & (B_SZ - 1);
    int t = e >> 13;

    // ---- prework (overlaps with precompute) ----
    const float* xp = x_seq + ((size_t)t * B_SZ + b) * 3;
    float x0 = xp[0], x1 = xp[1], x2 = xp[2];
    float s0, c0, s1, c1, s2, c2;
    __sincosf(x0, &s0, &c0);
    __sincosf(x1, &s1, &c1);
    __sincosf(x2, &s2, &c2);
    float g0[3] = {1.f, c0, s0};
    float g1[3] = {1.f, c1, s1};
    float g2[3] = {1.f, c2, s2};
    float P[27];
#pragma unroll
    for (int m0 = 0; m0 < 3; m0++) {
#pragma unroll
        for (int m1 = 0; m1 < 3; m1++) {
            float p01 = g0[m0] * g1[m1];
#pragma unroll
            for (int m2 = 0; m2 < 3; m2++)
                P[(m0 * 3 + m1) * 3 + m2] = p01 * g2[m2];
        }
    }

    pdl_wait();
    for (int i = tid; i < 540; i += 256) Ts[i] = d_Tp[i];
    __syncthreads();

    unsigned long long acc[9];
#pragma unroll
    for (int q = 0; q < 9; q++) acc[q] = 0ull;

    unsigned tbase = (unsigned)__cvta_generic_to_shared(Ts);
#pragma unroll
    for (int mx = 0; mx < 27; mx++) {
        unsigned long long p2 = pk2(P[mx]);
        unsigned ra = tbase + mx * 80;
        unsigned long long t0, t1, t2, t3, t4, t5, t6, t7, t8;
        asm volatile("ld.shared.v2.b64 {%0,%1}, [%2];" : "=l"(t0), "=l"(t1) : "r"(ra));
        asm volatile("ld.shared.v2.b64 {%0,%1}, [%2];" : "=l"(t2), "=l"(t3) : "r"(ra + 16));
        asm volatile("ld.shared.v2.b64 {%0,%1}, [%2];" : "=l"(t4), "=l"(t5) : "r"(ra + 32));
        asm volatile("ld.shared.v2.b64 {%0,%1}, [%2];" : "=l"(t6), "=l"(t7) : "r"(ra + 48));
        asm volatile("ld.shared.b64 %0, [%1];"          : "=l"(t8)          : "r"(ra + 64));
        acc[0] = fma2(p2, t0, acc[0]);
        acc[1] = fma2(p2, t1, acc[1]);
        acc[2] = fma2(p2, t2, acc[2]);
        acc[3] = fma2(p2, t3, acc[3]);
        acc[4] = fma2(p2, t4, acc[4]);
        acc[5] = fma2(p2, t5, acc[5]);
        acc[6] = fma2(p2, t6, acc[6]);
        acc[7] = fma2(p2, t7, acc[7]);
        acc[8] = fma2(p2, t8, acc[8]);
    }

#pragma unroll
    for (int q = 0; q < 4; q++) {
        float l0, h0v, l1, h1v;
        asm("mov.b64 {%0,%1}, %2;" : "=f"(l0), "=f"(h0v) : "l"(acc[2 * q]));
        asm("mov.b64 {%0,%1}, %2;" : "=f"(l1), "=f"(h1v) : "l"(acc[2 * q + 1]));
        d_S4[((size_t)t * 5 + q) * B_SZ + b] = make_float4(l0, h0v, l1, h1v);
    }
    {
        float l8, h8;
        asm("mov.b64 {%0,%1}, %2;" : "=f"(l8), "=f"(h8) : "l"(acc[8]));
        d_S4[((size_t)t * 5 + 4) * B_SZ + b] = make_float4(l8, h8, 0.f, 0.f);
    }
}

// ---------------------------------------------------------------------------
// Phase 2 (PDL): recurrence with cp.async-staged S (L2-hot).
// ---------------------------------------------------------------------------
__global__ void __launch_bounds__(64) phase2_kernel(float* __restrict__ out) {
    __shared__ __align__(16) float4 sbuf[8][5][64];   // 40KB
    const int tid = threadIdx.x;
    const int b = blockIdx.x * 64 + tid;

    pdl_wait();

#pragma unroll
    for (int t = 0; t < 7; t++) {
#pragma unroll
        for (int q = 0; q < 5; q++)
            cpa16(&sbuf[t][q][tid], &d_S4[((size_t)t * 5 + q) * B_SZ + b]);
        asm volatile("cp.async.commit_group;" ::: "memory");
    }

    float h0 = 0.f, h1 = 0.f;
#pragma unroll
    for (int t = 0; t < T_SZ; t++) {
        asm volatile("cp.async.wait_group 6;" ::: "memory");
        float4 v[5];
#pragma unroll
        for (int q = 0; q < 5; q++) v[q] = sbuf[t & 7][q][tid];

        if (t + 7 < T_SZ) {
#pragma unroll
            for (int q = 0; q < 5; q++)
                cpa16(&sbuf[(t + 7) & 7][q][tid],
                      &d_S4[((size_t)(t + 7) * 5 + q) * B_SZ + b]);
        }
        asm volatile("cp.async.commit_group;" ::: "memory");

        float Sc[20];
#pragma unroll
        for (int q = 0; q < 5; q++) {
            Sc[4 * q + 0] = v[q].x;
            Sc[4 * q + 1] = v[q].y;
            Sc[4 * q + 2] = v[q].z;
            Sc[4 * q + 3] = v[q].w;
        }
        float sh0, ch0, sh1, ch1;
        __sincosf(h0, &sh0, &ch0);
        __sincosf(h1, &sh1, &ch1);
        float Q[9];
        Q[0] = 1.f;        Q[1] = ch1;        Q[2] = sh1;
        Q[3] = ch0;        Q[4] = ch0 * ch1;  Q[5] = ch0 * sh1;
        Q[6] = sh0;        Q[7] = sh0 * ch1;  Q[8] = sh0 * sh1;
        float a0 = 0.f, a1 = 0.f;
#pragma unroll
        for (int mh = 0; mh < 9; mh++) {
            a0 += Sc[2 * mh] * Q[mh];
            a1 += Sc[2 * mh + 1] * Q[mh];
        }
        h0 = a0;
        h1 = a1;
    }

    // Readout
    float To[9];
#pragma unroll
    for (int i = 0; i < 9; i++) To[i] = d_To[i];
    float sh0, ch0, sh1, ch1;
    __sincosf(h0, &sh0, &ch0);
    __sincosf(h1, &sh1, &ch1);
    float Q[9] = {1.f, ch1, sh1, ch0, ch0 * ch1, ch0 * sh1,
                  sh0, sh0 * ch1, sh0 * sh1};
    float r = 0.f;
#pragma unroll
    for (int m = 0; m < 9; m++) r += To[m] * Q[m];
    out[b] = r;
}

// ---------------------------------------------------------------------------
extern "C" void kernel_launch(void* const* d_in, const int* in_sizes, int n_in,
                              void* d_out, int out_size) {
    const float* x_seq = nullptr;
    const float* w_rec = nullptr;
    const float* w_out = nullptr;
    for (int i = 0; i < n_in; i++) {
        if (in_sizes[i] == T_SZ * B_SZ * 3) x_seq = (const float*)d_in[i];
        else if (in_sizes[i] == 30)         w_rec = (const float*)d_in[i];
        else if (in_sizes[i] == 12)         w_out = (const float*)d_in[i];
    }
    float* out = (float*)d_out;

    precompute_kernel<<<9, 256>>>(w_rec, w_out);

    {
        cudaLaunchConfig_t cfg = {};
        cfg.gridDim = dim3((T_SZ * B_SZ) / 256);
        cfg.blockDim = dim3(256);
        cudaLaunchAttribute attr[1];
        attr[0].id = cudaLaunchAttributeProgrammaticStreamSerialization;
        attr[0].val.programmaticStreamSerializationAllowed = 1;
        cfg.attrs = attr;
        cfg.numAttrs = 1;
        cfg.stream = 0;
        cudaLaunchKernelEx(&cfg, phase1_kernel, x_seq);
    }
    {
        cudaLaunchConfig_t cfg = {};
        cfg.gridDim = dim3(B_SZ / 64);
        cfg.blockDim = dim3(64);
        cudaLaunchAttribute attr[1];
        attr[0].id = cudaLaunchAttributeProgrammaticStreamSerialization;
        attr[0].val.programmaticStreamSerializationAllowed = 1;
        cfg.attrs = attr;
        cfg.numAttrs = 1;
        cfg.stream = 0;
        cudaLaunchKernelEx(&cfg, phase2_kernel, out);
    }
}

// round 11
// speedup vs baseline: 1.0440x; 1.0440x over previous
#include <cuda_runtime.h>

#define B_SZ 8192
#define T_SZ 32

__device__ __forceinline__ float2 cmul(float2 a, float2 b) {
    return make_float2(a.x * b.x - a.y * b.y, a.x * b.y + a.y * b.x);
}
__device__ __forceinline__ unsigned long long fma2(unsigned long long a,
                                                   unsigned long long b,
                                                   unsigned long long c) {
    unsigned long long d;
    asm("fma.rn.f32x2 %0, %1, %2, %3;" : "=l"(d) : "l"(a), "l"(b), "l"(c));
    return d;
}
__device__ __forceinline__ unsigned long long pk2(float x) {
    unsigned long long r;
    asm("mov.b64 %0, {%1, %1};" : "=l"(r) : "f"(x));
    return r;
}

// ---------------------------------------------------------------------------
// Single fused kernel. 128 blocks x 256 threads; block owns 64 batch elems.
//   Part A (per block, ~1.3us): shuffle-built U -> M-diagonals (all 32
//          xmasks) -> in-warp WHT -> T tensor in shared.
//   Part B: 8-stage producer/consumer pipeline. All 256 threads produce
//          S-vectors (243 fma2) into double-buffered smem; threads 0..63
//          run the recurrence. S never touches global memory.
// ---------------------------------------------------------------------------
__global__ void __launch_bounds__(256) mega_kernel(
        const float* __restrict__ x_seq,
        const float* __restrict__ wrec,
        const float* __restrict__ wout,
        float* __restrict__ out) {
    __shared__ float2 G[10][4];
    __shared__ __align__(16) float s_Ts[540];
    __shared__ float s_To[9];
    __shared__ __align__(16) char s_mem[40960];   // Us (8448B) / buf (40960B) union

    const int tid  = threadIdx.x;
    const int lane = tid & 31;
    const int wid  = tid >> 5;

    float2* Us  = (float2*)s_mem;                 // [32][33] row-major, row = state
    float4* buf = (float4*)s_mem;                 // [2][4][5][64]

    // ---- x prefetch for stage 0 (thread's pair: b = tid&63, t_local = tid>>6)
    const int pb  = blockIdx.x * 64 + (tid & 63);
    const int pt0 = tid >> 6;
    const float* xbase = x_seq + ((size_t)pt0 * B_SZ + pb) * 3;
    float xc0 = __ldg(xbase + 0), xc1 = __ldg(xbase + 1), xc2 = __ldg(xbase + 2);

    // ---- gates + Ts pads ----
    if (tid < 10) {
        float phi = wrec[tid * 3 + 0];
        float th  = wrec[tid * 3 + 1];
        float om  = wrec[tid * 3 + 2];
        float s, c, sa, ca, sb, cb;
        __sincosf(0.5f * th, &s, &c);
        __sincosf(0.5f * (phi + om), &sa, &ca);
        __sincosf(0.5f * (phi - om), &sb, &cb);
        G[tid][0] = make_float2( c * ca, -c * sa);
        G[tid][1] = make_float2(-s * cb, -s * sb);
        G[tid][2] = make_float2( s * cb, -s * sb);
        G[tid][3] = make_float2( c * ca,  c * sa);
    }
    if (tid >= 128 && tid < 182) {
        int i = tid - 128;
        s_Ts[(i >> 1) * 20 + 18 + (i & 1)] = 0.f;
    }
    __syncthreads();

    // ---- U build: warp wid owns columns 4wid..4wid+3, lane = row (shfl) ----
    {
        const int colbase = wid * 4;
        float ar[4], ai[4];
#pragma unroll
        for (int cc = 0; cc < 4; cc++) {
            ar[cc] = (lane == colbase + cc) ? 1.f : 0.f;
            ai[cc] = 0.f;
        }
#pragma unroll
        for (int l = 0; l < 2; l++) {
#pragma unroll
            for (int w = 0; w < 5; w++) {
                const int m = 1 << (4 - w);
                const int gi = l * 5 + w;
                float2 g00 = G[gi][0], g01 = G[gi][1];
                float2 g10 = G[gi][2], g11 = G[gi][3];
                bool hi = (lane & m) != 0;
                float cSx = hi ? g11.x : g00.x;
                float cSy = hi ? g11.y : g00.y;
                float cPx = hi ? g10.x : g01.x;
                float cPy = hi ? g10.y : g01.y;
#pragma unroll
                for (int cc = 0; cc < 4; cc++) {
                    float arp = __shfl_xor_sync(0xffffffffu, ar[cc], m);
                    float aip = __shfl_xor_sync(0xffffffffu, ai[cc], m);
                    float nr = cSx * ar[cc] - cSy * ai[cc] + cPx * arp - cPy * aip;
                    float ni = cSx * ai[cc] + cSy * ar[cc] + cPx * aip + cPy * arp;
                    ar[cc] = nr;
                    ai[cc] = ni;
                }
            }
            // CNOT ring (range l+1): fused permutation via index shuffle
            {
                int rr = l + 1;
                int j = lane;
#pragma unroll
                for (int w = 4; w >= 0; w--) {
                    int cm = 1 << (4 - w);
                    int tm = 1 << (4 - ((w + rr) % 5));
                    if (j & cm) j ^= tm;
                }
#pragma unroll
                for (int cc = 0; cc < 4; cc++) {
                    ar[cc] = __shfl_sync(0xffffffffu, ar[cc], j);
                    ai[cc] = __shfl_sync(0xffffffffu, ai[cc], j);
                }
            }
        }
#pragma unroll
        for (int cc = 0; cc < 4; cc++)
            Us[lane * 33 + colbase + cc] = make_float2(ar[cc], ai[cc]);
    }
    __syncthreads();

    // ---- M-diagonals + in-warp WHT -> T (warp handles xm = wid + 8*it) ----
#pragma unroll
    for (int it = 0; it < 4; it++) {
        const int xm = wid + it * 8;
        const int v  = lane ^ xm;
        float m0 = 0.f, m1 = 0.f;
#pragma unroll
        for (int k = 0; k < 32; k++) {
            float2 a = Us[k * 33 + lane];
            float2 b = Us[k * 33 + v];
            float re = a.x * b.x + a.y * b.y;
            m0 += ((k >> 1) & 1) ? -re : re;
            m1 += (k & 1) ? -re : re;
        }
        // WHT: after 5 stages, lane e holds sum_u sgn(popc(u&e)) * f[u]
#pragma unroll
        for (int p = 0; p < 5; p++) {
            int bm = 1 << p;
            float q0 = __shfl_xor_sync(0xffffffffu, m0, bm);
            float q1 = __shfl_xor_sync(0xffffffffu, m1, bm);
            if (lane & bm) { m0 = q0 - m0; m1 = q1 - m1; }
            else           { m0 = m0 + q0; m1 = m1 + q1; }
        }
        if ((lane & xm) == 0) {
            int e = lane, m = 0, p3 = 1;
#pragma unroll
            for (int p = 0; p < 5; p++) {
                int t3 = (xm & (1 << p)) ? 2 : ((e & (1 << p)) ? 1 : 0);
                m += t3 * p3;
                p3 *= 3;
            }
            s_Ts[(m / 9) * 20 + (m % 9) * 2 + 0] = m0 * (1.f / 32.f);
            s_Ts[(m / 9) * 20 + (m % 9) * 2 + 1] = m1 * (1.f / 32.f);
        }
    }
    __syncthreads();   // Us dead; buf area free; s_Ts ready

    // ---- pipeline: 8 stages x 4 timesteps ----
    const unsigned tbase = (unsigned)__cvta_generic_to_shared(s_Ts);
    float h0 = 0.f, h1 = 0.f;

#pragma unroll 1
    for (int s = 0; s < 8; s++) {
        // prefetch x for stage s+1
        float xn0 = 0.f, xn1 = 0.f, xn2 = 0.f;
        if (s < 7) {
            const float* p = xbase + (size_t)(s + 1) * (4 * B_SZ * 3);
            xn0 = __ldg(p + 0); xn1 = __ldg(p + 1); xn2 = __ldg(p + 2);
        }

        // consume previous stage (threads 0..63)
        if (tid < 64 && s > 0) {
            const int pbuf = (s - 1) & 1;
#pragma unroll
            for (int tl = 0; tl < 4; tl++) {
                float4 v[5];
#pragma unroll
                for (int q = 0; q < 5; q++)
                    v[q] = buf[((pbuf * 4 + tl) * 5 + q) * 64 + tid];
                float Sc[20];
#pragma unroll
                for (int q = 0; q < 5; q++) {
                    Sc[4 * q + 0] = v[q].x;
                    Sc[4 * q + 1] = v[q].y;
                    Sc[4 * q + 2] = v[q].z;
                    Sc[4 * q + 3] = v[q].w;
                }
                float sh0, ch0, sh1, ch1;
                __sincosf(h0, &sh0, &ch0);
                __sincosf(h1, &sh1, &ch1);
                float Q[9];
                Q[0] = 1.f;        Q[1] = ch1;        Q[2] = sh1;
                Q[3] = ch0;        Q[4] = ch0 * ch1;  Q[5] = ch0 * sh1;
                Q[6] = sh0;        Q[7] = sh0 * ch1;  Q[8] = sh0 * sh1;
                float a0 = 0.f, a1 = 0.f;
#pragma unroll
                for (int mh = 0; mh < 9; mh++) {
                    a0 += Sc[2 * mh] * Q[mh];
                    a1 += Sc[2 * mh + 1] * Q[mh];
                }
                h0 = a0;
                h1 = a1;
            }
        }

        // readout tensor To: once, threads 64..72, hidden under stage 0
        if (s == 0 && tid >= 64 && tid < 73) {
            int m = tid - 64;
            float2 V[4][4];
#pragma unroll
            for (int c2 = 0; c2 < 4; c2++)
#pragma unroll
                for (int r2 = 0; r2 < 4; r2++)
                    V[c2][r2] = make_float2(c2 == r2 ? 1.f : 0.f, 0.f);
#pragma unroll
            for (int l = 0; l < 2; l++) {
#pragma unroll
                for (int w = 0; w < 2; w++) {
                    float phi = wout[(l * 2 + w) * 3 + 0];
                    float th  = wout[(l * 2 + w) * 3 + 1];
                    float om  = wout[(l * 2 + w) * 3 + 2];
                    float sv, cv, sa, ca, sb, cb;
                    __sincosf(0.5f * th, &sv, &cv);
                    __sincosf(0.5f * (phi + om), &sa, &ca);
                    __sincosf(0.5f * (phi - om), &sb, &cb);
                    float2 r00 = make_float2( cv * ca, -cv * sa);
                    float2 r01 = make_float2(-sv * cb, -sv * sb);
                    float2 r10 = make_float2( sv * cb, -sv * sb);
                    float2 r11 = make_float2( cv * ca,  cv * sa);
                    int mask = 1 << (1 - w);
#pragma unroll
                    for (int col = 0; col < 4; col++) {
#pragma unroll
                        for (int i0 = 0; i0 < 4; i0++) {
                            if (i0 & mask) continue;
                            int i1 = i0 | mask;
                            float2 a0 = V[col][i0], a1 = V[col][i1];
                            float2 n0 = cmul(r00, a0), u01 = cmul(r01, a1);
                            n0.x += u01.x; n0.y += u01.y;
                            float2 n1 = cmul(r10, a0), u11 = cmul(r11, a1);
                            n1.x += u11.x; n1.y += u11.y;
                            V[col][i0] = n0;
                            V[col][i1] = n1;
                        }
                    }
                }
#pragma unroll
                for (int w = 0; w < 2; w++) {
                    int cm = 1 << (1 - w), tm = 1 << (1 - ((w + 1) & 1));
#pragma unroll
                    for (int col = 0; col < 4; col++)
#pragma unroll
                        for (int row = 0; row < 4; row++)
                            if ((row & cm) && !(row & tm)) {
                                float2 a = V[col][row], b2 = V[col][row | tm];
                                V[col][row] = b2;
                                V[col][row | tm] = a;
                            }
                }
            }
            float Mo[4][4];
#pragma unroll
            for (int ss = 0; ss < 4; ss++)
#pragma unroll
                for (int tt = 0; tt < 4; tt++) {
                    float acc = 0.f;
#pragma unroll
                    for (int k = 0; k < 4; k++) {
                        float2 vs = V[ss][k], vt = V[tt][k];
                        float re = vs.x * vt.x + vs.y * vt.y;
                        acc += ((k >> 1) & 1) ? -re : re;
                    }
                    Mo[ss][tt] = acc;
                }
            int d0 = m / 3, d1 = m % 3;
            int emask = (d0 == 1 ? 2 : 0) | (d1 == 1 ? 1 : 0);
            int xmask = (d0 == 2 ? 2 : 0) | (d1 == 2 ? 1 : 0);
            float sum = 0.f;
#pragma unroll
            for (int u = 0; u < 4; u++) {
                float sgn = (__popc(u & emask) & 1) ? -1.f : 1.f;
                sum += sgn * Mo[u][u ^ xmask];
            }
            s_To[m] = sum * 0.25f;
        }

        // produce stage s into buf[s&1] (all 256 threads, one S-vector each)
        {
            float s0, c0, s1, c1, s2, c2;
            __sincosf(xc0, &s0, &c0);
            __sincosf(xc1, &s1, &c1);
            __sincosf(xc2, &s2, &c2);
            float g0[3] = {1.f, c0, s0};
            float g1[3] = {1.f, c1, s1};
            float g2[3] = {1.f, c2, s2};
            float P[27];
#pragma unroll
            for (int m0i = 0; m0i < 3; m0i++) {
#pragma unroll
                for (int m1i = 0; m1i < 3; m1i++) {
                    float p01 = g0[m0i] * g1[m1i];
#pragma unroll
                    for (int m2i = 0; m2i < 3; m2i++)
                        P[(m0i * 3 + m1i) * 3 + m2i] = p01 * g2[m2i];
                }
            }
            unsigned long long acc[9];
#pragma unroll
            for (int q = 0; q < 9; q++) acc[q] = 0ull;
#pragma unroll
            for (int mx = 0; mx < 27; mx++) {
                unsigned long long p2 = pk2(P[mx]);
                unsigned ra = tbase + mx * 80;
                unsigned long long t0, t1, t2, t3, t4, t5, t6, t7, t8;
                asm volatile("ld.shared.v2.b64 {%0,%1}, [%2];" : "=l"(t0), "=l"(t1) : "r"(ra));
                asm volatile("ld.shared.v2.b64 {%0,%1}, [%2];" : "=l"(t2), "=l"(t3) : "r"(ra + 16));
                asm volatile("ld.shared.v2.b64 {%0,%1}, [%2];" : "=l"(t4), "=l"(t5) : "r"(ra + 32));
                asm volatile("ld.shared.v2.b64 {%0,%1}, [%2];" : "=l"(t6), "=l"(t7) : "r"(ra + 48));
                asm volatile("ld.shared.b64 %0, [%1];"          : "=l"(t8)          : "r"(ra + 64));
                acc[0] = fma2(p2, t0, acc[0]);
                acc[1] = fma2(p2, t1, acc[1]);
                acc[2] = fma2(p2, t2, acc[2]);
                acc[3] = fma2(p2, t3, acc[3]);
                acc[4] = fma2(p2, t4, acc[4]);
                acc[5] = fma2(p2, t5, acc[5]);
                acc[6] = fma2(p2, t6, acc[6]);
                acc[7] = fma2(p2, t7, acc[7]);
                acc[8] = fma2(p2, t8, acc[8]);
            }
            const int b64 = tid & 63;
            const int base = (((s & 1) * 4 + pt0) * 5) * 64 + b64;
#pragma unroll
            for (int q = 0; q < 4; q++) {
                float l0, h0v, l1, h1v;
                asm("mov.b64 {%0,%1}, %2;" : "=f"(l0), "=f"(h0v) : "l"(acc[2 * q]));
                asm("mov.b64 {%0,%1}, %2;" : "=f"(l1), "=f"(h1v) : "l"(acc[2 * q + 1]));
                buf[base + q * 64] = make_float4(l0, h0v, l1, h1v);
            }
            {
                float l8, h8;
                asm("mov.b64 {%0,%1}, %2;" : "=f"(l8), "=f"(h8) : "l"(acc[8]));
                buf[base + 4 * 64] = make_float4(l8, h8, 0.f, 0.f);
            }
        }

        xc0 = xn0; xc1 = xn1; xc2 = xn2;
        __syncthreads();
    }

    // ---- final consume (stage 7) + readout ----
    if (tid < 64) {
#pragma unroll
        for (int tl = 0; tl < 4; tl++) {
            float4 v[5];
#pragma unroll
            for (int q = 0; q < 5; q++)
                v[q] = buf[((1 * 4 + tl) * 5 + q) * 64 + tid];   // stage 7 -> parity 1
            float Sc[20];
#pragma unroll
            for (int q = 0; q < 5; q++) {
                Sc[4 * q + 0] = v[q].x;
                Sc[4 * q + 1] = v[q].y;
                Sc[4 * q + 2] = v[q].z;
                Sc[4 * q + 3] = v[q].w;
            }
            float sh0, ch0, sh1, ch1;
            __sincosf(h0, &sh0, &ch0);
            __sincosf(h1, &sh1, &ch1);
            float Q[9];
            Q[0] = 1.f;        Q[1] = ch1;        Q[2] = sh1;
            Q[3] = ch0;        Q[4] = ch0 * ch1;  Q[5] = ch0 * sh1;
            Q[6] = sh0;        Q[7] = sh0 * ch1;  Q[8] = sh0 * sh1;
            float a0 = 0.f, a1 = 0.f;
#pragma unroll
            for (int mh = 0; mh < 9; mh++) {
                a0 += Sc[2 * mh] * Q[mh];
                a1 += Sc[2 * mh + 1] * Q[mh];
            }
            h0 = a0;
            h1 = a1;
        }
        float sh0, ch0, sh1, ch1;
        __sincosf(h0, &sh0, &ch0);
        __sincosf(h1, &sh1, &ch1);
        float Q[9] = {1.f, ch1, sh1, ch0, ch0 * ch1, ch0 * sh1,
                      sh0, sh0 * ch1, sh0 * sh1};
        float r = 0.f;
#pragma unroll
        for (int m = 0; m < 9; m++) r += s_To[m] * Q[m];
        out[blockIdx.x * 64 + tid] = r;
    }
}

// ---------------------------------------------------------------------------
extern "C" void kernel_launch(void* const* d_in, const int* in_sizes, int n_in,
                              void* d_out, int out_size) {
    const float* x_seq = nullptr;
    const float* w_rec = nullptr;
    const float* w_out = nullptr;
    for (int i = 0; i < n_in; i++) {
        if (in_sizes[i] == T_SZ * B_SZ * 3) x_seq = (const float*)d_in[i];
        else if (in_sizes[i] == 30)         w_rec = (const float*)d_in[i];
        else if (in_sizes[i] == 12)         w_out = (const float*)d_in[i];
    }
    float* out = (float*)d_out;

    mega_kernel<<<B_SZ / 64, 256>>>(x_seq, w_rec, w_out, out);
}

// round 12
// speedup vs baseline: 1.2576x; 1.2045x over previous
#include <cuda_runtime.h>

#define B_SZ 8192
#define T_SZ 32
#define SMEM_BYTES 81920   // buf [2][8][5][64] float4

__device__ __forceinline__ float2 cmul(float2 a, float2 b) {
    return make_float2(a.x * b.x - a.y * b.y, a.x * b.y + a.y * b.x);
}
__device__ __forceinline__ unsigned long long fma2(unsigned long long a,
                                                   unsigned long long b,
                                                   unsigned long long c) {
    unsigned long long d;
    asm("fma.rn.f32x2 %0, %1, %2, %3;" : "=l"(d) : "l"(a), "l"(b), "l"(c));
    return d;
}
__device__ __forceinline__ unsigned long long pk2(float x) {
    unsigned long long r;
    asm("mov.b64 %0, {%1, %1};" : "=l"(r) : "f"(x));
    return r;
}

// ---------------------------------------------------------------------------
// Single fused kernel. 128 blocks x 256 threads; block owns 64 batch elems.
//   Part A: shuffle-built U -> M-diagonals (32 xmasks) -> WHT -> T in smem.
//   Part B: 4 stages x 8 timesteps. Each thread produces TWO S-vectors per
//           stage sharing all T loads (halves LDS, doubles FMA ILP).
//           Threads 0..63 consume the previous stage (8 recurrence steps),
//           placed AFTER produce so the serial chain interleaves.
// ---------------------------------------------------------------------------
__global__ void __launch_bounds__(256) mega_kernel(
        const float* __restrict__ x_seq,
        const float* __restrict__ wrec,
        const float* __restrict__ wout,
        float* __restrict__ out) {
    __shared__ float2 G[10][4];
    __shared__ __align__(16) float s_Ts[540];
    __shared__ float s_To[9];
    extern __shared__ __align__(16) char s_mem[];   // 80KB dynamic

    const int tid  = threadIdx.x;
    const int lane = tid & 31;
    const int wid  = tid >> 5;

    float2* Us  = (float2*)s_mem;                 // [32][33] during T-build
    float4* buf = (float4*)s_mem;                 // [2][8][5][64] after

    // thread's production slots: b = tid&63, timesteps tl0, tl0+1 per stage
    const int b64 = tid & 63;
    const int pb  = blockIdx.x * 64 + b64;
    const int tl0 = (tid >> 6) * 2;

    // ---- x prefetch for stage 0 ----
    const float* xA = x_seq + ((size_t)tl0 * B_SZ + pb) * 3;
    const float* xB = x_seq + ((size_t)(tl0 + 1) * B_SZ + pb) * 3;
    float xa0 = __ldg(xA + 0), xa1 = __ldg(xA + 1), xa2 = __ldg(xA + 2);
    float xb0 = __ldg(xB + 0), xb1 = __ldg(xB + 1), xb2 = __ldg(xB + 2);

    // ---- gates + Ts pads ----
    if (tid < 10) {
        float phi = wrec[tid * 3 + 0];
        float th  = wrec[tid * 3 + 1];
        float om  = wrec[tid * 3 + 2];
        float s, c, sa, ca, sb, cb;
        __sincosf(0.5f * th, &s, &c);
        __sincosf(0.5f * (phi + om), &sa, &ca);
        __sincosf(0.5f * (phi - om), &sb, &cb);
        G[tid][0] = make_float2( c * ca, -c * sa);
        G[tid][1] = make_float2(-s * cb, -s * sb);
        G[tid][2] = make_float2( s * cb, -s * sb);
        G[tid][3] = make_float2( c * ca,  c * sa);
    }
    if (tid >= 128 && tid < 182) {
        int i = tid - 128;
        s_Ts[(i >> 1) * 20 + 18 + (i & 1)] = 0.f;
    }
    __syncthreads();

    // ---- U build via shuffles (warp wid owns cols 4wid..4wid+3) ----
    {
        const int colbase = wid * 4;
        float ar[4], ai[4];
#pragma unroll
        for (int cc = 0; cc < 4; cc++) {
            ar[cc] = (lane == colbase + cc) ? 1.f : 0.f;
            ai[cc] = 0.f;
        }
#pragma unroll
        for (int l = 0; l < 2; l++) {
#pragma unroll
            for (int w = 0; w < 5; w++) {
                const int m = 1 << (4 - w);
                const int gi = l * 5 + w;
                float2 g00 = G[gi][0], g01 = G[gi][1];
                float2 g10 = G[gi][2], g11 = G[gi][3];
                bool hi = (lane & m) != 0;
                float cSx = hi ? g11.x : g00.x;
                float cSy = hi ? g11.y : g00.y;
                float cPx = hi ? g10.x : g01.x;
                float cPy = hi ? g10.y : g01.y;
#pragma unroll
                for (int cc = 0; cc < 4; cc++) {
                    float arp = __shfl_xor_sync(0xffffffffu, ar[cc], m);
                    float aip = __shfl_xor_sync(0xffffffffu, ai[cc], m);
                    float nr = cSx * ar[cc] - cSy * ai[cc] + cPx * arp - cPy * aip;
                    float ni = cSx * ai[cc] + cSy * ar[cc] + cPx * aip + cPy * arp;
                    ar[cc] = nr;
                    ai[cc] = ni;
                }
            }
            {
                int rr = l + 1;
                int j = lane;
#pragma unroll
                for (int w = 4; w >= 0; w--) {
                    int cm = 1 << (4 - w);
                    int tm = 1 << (4 - ((w + rr) % 5));
                    if (j & cm) j ^= tm;
                }
#pragma unroll
                for (int cc = 0; cc < 4; cc++) {
                    ar[cc] = __shfl_sync(0xffffffffu, ar[cc], j);
                    ai[cc] = __shfl_sync(0xffffffffu, ai[cc], j);
                }
            }
        }
#pragma unroll
        for (int cc = 0; cc < 4; cc++)
            Us[lane * 33 + colbase + cc] = make_float2(ar[cc], ai[cc]);
    }
    __syncthreads();

    // ---- M-diagonals + WHT -> T (warp wid handles xm = wid + 8*it) ----
#pragma unroll
    for (int it = 0; it < 4; it++) {
        const int xm = wid + it * 8;
        const int v  = lane ^ xm;
        float m0 = 0.f, m1 = 0.f;
#pragma unroll
        for (int k = 0; k < 32; k++) {
            float2 a = Us[k * 33 + lane];
            float2 b = Us[k * 33 + v];
            float re = a.x * b.x + a.y * b.y;
            m0 += ((k >> 1) & 1) ? -re : re;
            m1 += (k & 1) ? -re : re;
        }
#pragma unroll
        for (int p = 0; p < 5; p++) {
            int bm = 1 << p;
            float q0 = __shfl_xor_sync(0xffffffffu, m0, bm);
            float q1 = __shfl_xor_sync(0xffffffffu, m1, bm);
            if (lane & bm) { m0 = q0 - m0; m1 = q1 - m1; }
            else           { m0 = m0 + q0; m1 = m1 + q1; }
        }
        if ((lane & xm) == 0) {
            int e = lane, m = 0, p3 = 1;
#pragma unroll
            for (int p = 0; p < 5; p++) {
                int t3 = (xm & (1 << p)) ? 2 : ((e & (1 << p)) ? 1 : 0);
                m += t3 * p3;
                p3 *= 3;
            }
            s_Ts[(m / 9) * 20 + (m % 9) * 2 + 0] = m0 * (1.f / 32.f);
            s_Ts[(m / 9) * 20 + (m % 9) * 2 + 1] = m1 * (1.f / 32.f);
        }
    }
    __syncthreads();   // Us dead; buf free; s_Ts ready

    const unsigned tbase = (unsigned)__cvta_generic_to_shared(s_Ts);
    float h0 = 0.f, h1 = 0.f;

#pragma unroll 1
    for (int s = 0; s < 4; s++) {
        // prefetch x for stage s+1
        float na0 = 0.f, na1 = 0.f, na2 = 0.f;
        float nb0 = 0.f, nb1 = 0.f, nb2 = 0.f;
        if (s < 3) {
            const float* pA = xA + (size_t)(s + 1) * (8 * B_SZ * 3);
            const float* pB = xB + (size_t)(s + 1) * (8 * B_SZ * 3);
            na0 = __ldg(pA + 0); na1 = __ldg(pA + 1); na2 = __ldg(pA + 2);
            nb0 = __ldg(pB + 0); nb1 = __ldg(pB + 1); nb2 = __ldg(pB + 2);
        }

        // ---- produce stage s: 2 S-vectors per thread, shared T loads ----
        {
            float sa0, ca0, sa1, ca1, sa2, ca2;
            float sb0, cb0, sb1, cb1, sb2, cb2;
            __sincosf(xa0, &sa0, &ca0);
            __sincosf(xa1, &sa1, &ca1);
            __sincosf(xa2, &sa2, &ca2);
            __sincosf(xb0, &sb0, &cb0);
            __sincosf(xb1, &sb1, &cb1);
            __sincosf(xb2, &sb2, &cb2);
            float g0a[3] = {1.f, ca0, sa0}, g1a[3] = {1.f, ca1, sa1}, g2a[3] = {1.f, ca2, sa2};
            float g0b[3] = {1.f, cb0, sb0}, g1b[3] = {1.f, cb1, sb1}, g2b[3] = {1.f, cb2, sb2};

            unsigned long long accA[9], accB[9];
#pragma unroll
            for (int q = 0; q < 9; q++) { accA[q] = 0ull; accB[q] = 0ull; }

#pragma unroll
            for (int m0i = 0; m0i < 3; m0i++) {
#pragma unroll
                for (int m1i = 0; m1i < 3; m1i++) {
                    float p01a = g0a[m0i] * g1a[m1i];
                    float p01b = g0b[m0i] * g1b[m1i];
#pragma unroll
                    for (int m2i = 0; m2i < 3; m2i++) {
                        unsigned long long pa = pk2(p01a * g2a[m2i]);
                        unsigned long long pb2 = pk2(p01b * g2b[m2i]);
                        int mx = (m0i * 3 + m1i) * 3 + m2i;
                        unsigned ra = tbase + mx * 80;
                        unsigned long long t0, t1, t2, t3, t4, t5, t6, t7, t8;
                        asm volatile("ld.shared.v2.b64 {%0,%1}, [%2];" : "=l"(t0), "=l"(t1) : "r"(ra));
                        asm volatile("ld.shared.v2.b64 {%0,%1}, [%2];" : "=l"(t2), "=l"(t3) : "r"(ra + 16));
                        asm volatile("ld.shared.v2.b64 {%0,%1}, [%2];" : "=l"(t4), "=l"(t5) : "r"(ra + 32));
                        asm volatile("ld.shared.v2.b64 {%0,%1}, [%2];" : "=l"(t6), "=l"(t7) : "r"(ra + 48));
                        asm volatile("ld.shared.b64 %0, [%1];"          : "=l"(t8)          : "r"(ra + 64));
                        accA[0] = fma2(pa, t0, accA[0]);  accB[0] = fma2(pb2, t0, accB[0]);
                        accA[1] = fma2(pa, t1, accA[1]);  accB[1] = fma2(pb2, t1, accB[1]);
                        accA[2] = fma2(pa, t2, accA[2]);  accB[2] = fma2(pb2, t2, accB[2]);
                        accA[3] = fma2(pa, t3, accA[3]);  accB[3] = fma2(pb2, t3, accB[3]);
                        accA[4] = fma2(pa, t4, accA[4]);  accB[4] = fma2(pb2, t4, accB[4]);
                        accA[5] = fma2(pa, t5, accA[5]);  accB[5] = fma2(pb2, t5, accB[5]);
                        accA[6] = fma2(pa, t6, accA[6]);  accB[6] = fma2(pb2, t6, accB[6]);
                        accA[7] = fma2(pa, t7, accA[7]);  accB[7] = fma2(pb2, t7, accB[7]);
                        accA[8] = fma2(pa, t8, accA[8]);  accB[8] = fma2(pb2, t8, accB[8]);
                    }
                }
            }

            const int par = s & 1;
            const int baseA = ((par * 8 + tl0) * 5) * 64 + b64;
            const int baseB = ((par * 8 + tl0 + 1) * 5) * 64 + b64;
#pragma unroll
            for (int q = 0; q < 4; q++) {
                float l0, h0v, l1, h1v;
                asm("mov.b64 {%0,%1}, %2;" : "=f"(l0), "=f"(h0v) : "l"(accA[2 * q]));
                asm("mov.b64 {%0,%1}, %2;" : "=f"(l1), "=f"(h1v) : "l"(accA[2 * q + 1]));
                buf[baseA + q * 64] = make_float4(l0, h0v, l1, h1v);
            }
            {
                float l8, h8;
                asm("mov.b64 {%0,%1}, %2;" : "=f"(l8), "=f"(h8) : "l"(accA[8]));
                buf[baseA + 4 * 64] = make_float4(l8, h8, 0.f, 0.f);
            }
#pragma unroll
            for (int q = 0; q < 4; q++) {
                float l0, h0v, l1, h1v;
                asm("mov.b64 {%0,%1}, %2;" : "=f"(l0), "=f"(h0v) : "l"(accB[2 * q]));
                asm("mov.b64 {%0,%1}, %2;" : "=f"(l1), "=f"(h1v) : "l"(accB[2 * q + 1]));
                buf[baseB + q * 64] = make_float4(l0, h0v, l1, h1v);
            }
            {
                float l8, h8;
                asm("mov.b64 {%0,%1}, %2;" : "=f"(l8), "=f"(h8) : "l"(accB[8]));
                buf[baseB + 4 * 64] = make_float4(l8, h8, 0.f, 0.f);
            }
        }

        // ---- consume stage s-1 (threads 0..63, 8 steps) ----
        if (tid < 64 && s > 0) {
            const int pbuf = (s - 1) & 1;
#pragma unroll
            for (int tl = 0; tl < 8; tl++) {
                float4 v[5];
#pragma unroll
                for (int q = 0; q < 5; q++)
                    v[q] = buf[((pbuf * 8 + tl) * 5 + q) * 64 + tid];
                float Sc[20];
#pragma unroll
                for (int q = 0; q < 5; q++) {
                    Sc[4 * q + 0] = v[q].x;
                    Sc[4 * q + 1] = v[q].y;
                    Sc[4 * q + 2] = v[q].z;
                    Sc[4 * q + 3] = v[q].w;
                }
                float sh0, ch0, sh1, ch1;
                __sincosf(h0, &sh0, &ch0);
                __sincosf(h1, &sh1, &ch1);
                float Q[9];
                Q[0] = 1.f;        Q[1] = ch1;        Q[2] = sh1;
                Q[3] = ch0;        Q[4] = ch0 * ch1;  Q[5] = ch0 * sh1;
                Q[6] = sh0;        Q[7] = sh0 * ch1;  Q[8] = sh0 * sh1;
                float a0 = 0.f, a1 = 0.f;
#pragma unroll
                for (int mh = 0; mh < 9; mh++) {
                    a0 += Sc[2 * mh] * Q[mh];
                    a1 += Sc[2 * mh + 1] * Q[mh];
                }
                h0 = a0;
                h1 = a1;
            }
        }

        // ---- readout tensor To: threads 64..72, hidden under stage 0 ----
        if (s == 0 && tid >= 64 && tid < 73) {
            int m = tid - 64;
            float2 V[4][4];
#pragma unroll
            for (int c2 = 0; c2 < 4; c2++)
#pragma unroll
                for (int r2 = 0; r2 < 4; r2++)
                    V[c2][r2] = make_float2(c2 == r2 ? 1.f : 0.f, 0.f);
#pragma unroll
            for (int l = 0; l < 2; l++) {
#pragma unroll
                for (int w = 0; w < 2; w++) {
                    float phi = wout[(l * 2 + w) * 3 + 0];
                    float th  = wout[(l * 2 + w) * 3 + 1];
                    float om  = wout[(l * 2 + w) * 3 + 2];
                    float sv, cv, sa, ca, sb, cb;
                    __sincosf(0.5f * th, &sv, &cv);
                    __sincosf(0.5f * (phi + om), &sa, &ca);
                    __sincosf(0.5f * (phi - om), &sb, &cb);
                    float2 r00 = make_float2( cv * ca, -cv * sa);
                    float2 r01 = make_float2(-sv * cb, -sv * sb);
                    float2 r10 = make_float2( sv * cb, -sv * sb);
                    float2 r11 = make_float2( cv * ca,  cv * sa);
                    int mask = 1 << (1 - w);
#pragma unroll
                    for (int col = 0; col < 4; col++) {
#pragma unroll
                        for (int i0 = 0; i0 < 4; i0++) {
                            if (i0 & mask) continue;
                            int i1 = i0 | mask;
                            float2 a0 = V[col][i0], a1 = V[col][i1];
                            float2 n0 = cmul(r00, a0), u01 = cmul(r01, a1);
                            n0.x += u01.x; n0.y += u01.y;
                            float2 n1 = cmul(r10, a0), u11 = cmul(r11, a1);
                            n1.x += u11.x; n1.y += u11.y;
                            V[col][i0] = n0;
                            V[col][i1] = n1;
                        }
                    }
                }
#pragma unroll
                for (int w = 0; w < 2; w++) {
                    int cm = 1 << (1 - w), tm = 1 << (1 - ((w + 1) & 1));
#pragma unroll
                    for (int col = 0; col < 4; col++)
#pragma unroll
                        for (int row = 0; row < 4; row++)
                            if ((row & cm) && !(row & tm)) {
                                float2 a = V[col][row], b2 = V[col][row | tm];
                                V[col][row] = b2;
                                V[col][row | tm] = a;
                            }
                }
            }
            float Mo[4][4];
#pragma unroll
            for (int ss = 0; ss < 4; ss++)
#pragma unroll
                for (int tt = 0; tt < 4; tt++) {
                    float acc = 0.f;
#pragma unroll
                    for (int k = 0; k < 4; k++) {
                        float2 vs = V[ss][k], vt = V[tt][k];
                        float re = vs.x * vt.x + vs.y * vt.y;
                        acc += ((k >> 1) & 1) ? -re : re;
                    }
                    Mo[ss][tt] = acc;
                }
            int d0 = m / 3, d1 = m % 3;
            int emask = (d0 == 1 ? 2 : 0) | (d1 == 1 ? 1 : 0);
            int xmask = (d0 == 2 ? 2 : 0) | (d1 == 2 ? 1 : 0);
            float sum = 0.f;
#pragma unroll
            for (int u = 0; u < 4; u++) {
                float sgn = (__popc(u & emask) & 1) ? -1.f : 1.f;
                sum += sgn * Mo[u][u ^ xmask];
            }
            s_To[m] = sum * 0.25f;
        }

        xa0 = na0; xa1 = na1; xa2 = na2;
        xb0 = nb0; xb1 = nb1; xb2 = nb2;
        __syncthreads();
    }

    // ---- final consume (stage 3, parity 1) + readout ----
    if (tid < 64) {
#pragma unroll
        for (int tl = 0; tl < 8; tl++) {
            float4 v[5];
#pragma unroll
            for (int q = 0; q < 5; q++)
                v[q] = buf[((1 * 8 + tl) * 5 + q) * 64 + tid];
            float Sc[20];
#pragma unroll
            for (int q = 0; q < 5; q++) {
                Sc[4 * q + 0] = v[q].x;
                Sc[4 * q + 1] = v[q].y;
                Sc[4 * q + 2] = v[q].z;
                Sc[4 * q + 3] = v[q].w;
            }
            float sh0, ch0, sh1, ch1;
            __sincosf(h0, &sh0, &ch0);
            __sincosf(h1, &sh1, &ch1);
            float Q[9];
            Q[0] = 1.f;        Q[1] = ch1;        Q[2] = sh1;
            Q[3] = ch0;        Q[4] = ch0 * ch1;  Q[5] = ch0 * sh1;
            Q[6] = sh0;        Q[7] = sh0 * ch1;  Q[8] = sh0 * sh1;
            float a0 = 0.f, a1 = 0.f;
#pragma unroll
            for (int mh = 0; mh < 9; mh++) {
                a0 += Sc[2 * mh] * Q[mh];
                a1 += Sc[2 * mh + 1] * Q[mh];
            }
            h0 = a0;
            h1 = a1;
        }
        float sh0, ch0, sh1, ch1;
        __sincosf(h0, &sh0, &ch0);
        __sincosf(h1, &sh1, &ch1);
        float Q[9] = {1.f, ch1, sh1, ch0, ch0 * ch1, ch0 * sh1,
                      sh0, sh0 * ch1, sh0 * sh1};
        float r = 0.f;
#pragma unroll
        for (int m = 0; m < 9; m++) r += s_To[m] * Q[m];
        out[blockIdx.x * 64 + tid] = r;
    }
}

// ---------------------------------------------------------------------------
extern "C" void kernel_launch(void* const* d_in, const int* in_sizes, int n_in,
                              void* d_out, int out_size) {
    const float* x_seq = nullptr;
    const float* w_rec = nullptr;
    const float* w_out = nullptr;
    for (int i = 0; i < n_in; i++) {
        if (in_sizes[i] == T_SZ * B_SZ * 3) x_seq = (const float*)d_in[i];
        else if (in_sizes[i] == 30)         w_rec = (const float*)d_in[i];
        else if (in_sizes[i] == 12)         w_out = (const float*)d_in[i];
    }
    float* out = (float*)d_out;

    cudaFuncSetAttribute(mega_kernel,
                         cudaFuncAttributeMaxDynamicSharedMemorySize, SMEM_BYTES);
    mega_kernel<<<B_SZ / 64, 256, SMEM_BYTES>>>(x_seq, w_rec, w_out, out);
}